// round 5
// baseline (speedup 1.0000x reference)
#include <cuda_runtime.h>
#include <cstddef>

#define HW   4096
#define CIN  256
#define CHD  128   // Q/K channel dim
#define MT   64    // query tile
#define NT   64    // key tile
#define BB   4

// Scratch for projected Q, K, V  (device globals: allocation-free)
__device__ float g_Q[BB * CHD * HW];
__device__ float g_K[BB * CHD * HW];
__device__ float g_V[BB * CIN * HW];

// ---------------------------------------------------------------------------
// Projection GEMM: Out[b, o, n] = sum_c W[o,c] * X[b,c,n] + bias[o]
// grid (HW/64, O/64, B), block 256.  64x64 tile, K-chunk 32, 4x4 per thread.
// ---------------------------------------------------------------------------
__global__ __launch_bounds__(256)
void proj_kernel(const float* __restrict__ W, const float* __restrict__ bias,
                 const float* __restrict__ X, float* __restrict__ Out, int O) {
    __shared__ float Ws[32][65];   // [k][o]  (padded)
    __shared__ float Xs[32][64];   // [k][n]

    const int tid = threadIdx.x;
    const int n0  = blockIdx.x * 64;
    const int o0  = blockIdx.y * 64;
    const int b   = blockIdx.z;
    const float* Xb = X + (size_t)b * CIN * HW;

    const int tx = tid & 15;       // n quad
    const int ty = tid >> 4;       // o quad
    float acc[4][4] = {};

    for (int k0 = 0; k0 < CIN; k0 += 32) {
        // --- load W tile: 64 rows(o) x 32 cols(k), 8 floats/thread ---
        {
            int r = tid >> 2;
            int q = (tid & 3) * 8;
            float4 wa = *(const float4*)&W[(size_t)(o0 + r) * CIN + k0 + q];
            float4 wb = *(const float4*)&W[(size_t)(o0 + r) * CIN + k0 + q + 4];
            Ws[q + 0][r] = wa.x; Ws[q + 1][r] = wa.y;
            Ws[q + 2][r] = wa.z; Ws[q + 3][r] = wa.w;
            Ws[q + 4][r] = wb.x; Ws[q + 5][r] = wb.y;
            Ws[q + 6][r] = wb.z; Ws[q + 7][r] = wb.w;
        }
        // --- load X tile: 32 rows(k) x 64 cols(n), 8 floats/thread ---
        {
            int c  = tid >> 3;
            int nq = (tid & 7) * 8;
            const float* src = &Xb[(size_t)(k0 + c) * HW + n0 + nq];
            *(float4*)&Xs[c][nq]     = *(const float4*)&src[0];
            *(float4*)&Xs[c][nq + 4] = *(const float4*)&src[4];
        }
        __syncthreads();

        #pragma unroll
        for (int kk = 0; kk < 32; kk++) {
            float4 xv = *(float4*)&Xs[kk][tx * 4];
            float w0 = Ws[kk][ty * 4 + 0];
            float w1 = Ws[kk][ty * 4 + 1];
            float w2 = Ws[kk][ty * 4 + 2];
            float w3 = Ws[kk][ty * 4 + 3];
            acc[0][0] += w0 * xv.x; acc[0][1] += w0 * xv.y; acc[0][2] += w0 * xv.z; acc[0][3] += w0 * xv.w;
            acc[1][0] += w1 * xv.x; acc[1][1] += w1 * xv.y; acc[1][2] += w1 * xv.z; acc[1][3] += w1 * xv.w;
            acc[2][0] += w2 * xv.x; acc[2][1] += w2 * xv.y; acc[2][2] += w2 * xv.z; acc[2][3] += w2 * xv.w;
            acc[3][0] += w3 * xv.x; acc[3][1] += w3 * xv.y; acc[3][2] += w3 * xv.z; acc[3][3] += w3 * xv.w;
        }
        __syncthreads();
    }

    #pragma unroll
    for (int i = 0; i < 4; i++) {
        int o = o0 + ty * 4 + i;
        float bi = bias[o];
        float4 r;
        r.x = acc[i][0] + bi; r.y = acc[i][1] + bi;
        r.z = acc[i][2] + bi; r.w = acc[i][3] + bi;
        *(float4*)&Out[((size_t)b * O + o) * HW + n0 + tx * 4] = r;
    }
}

// ---------------------------------------------------------------------------
// Flash attention + residual.
// grid (HW/MT, B), block 256, dynamic smem 87040 B, 2 blocks/SM.
// Thread t: mi = t&31, grp = t>>5.  Owns rows m0=mi, m1=mi+32.
//   S-phase: grp selects 8 n's.  O-phase: grp selects 32 output channels.
// ---------------------------------------------------------------------------
__global__ __launch_bounds__(256, 2)
void attn_kernel(const float* __restrict__ resid, float* __restrict__ out) {
    extern __shared__ float sm[];
    float* Qs     = sm;              // [128][64]  8192
    float* Ks     = Qs + 8192;       // [128][64]  8192
    float* Ss     = Ks + 8192;       // [NT][MT]   4096  (Ss[n][m])
    float* rowmax = Ss + 4096;       // 64
    float* rowsum = rowmax + 64;     // 64
    float* salpha = rowsum + 64;     // 64
    float* snmax  = salpha + 64;     // 64
    float* lmax   = snmax + 64;      // [8][64] 512
    float* lsum   = lmax + 512;      // [8][64] 512

    const int tid = threadIdx.x;
    const int b   = blockIdx.y;
    const int m0g = blockIdx.x * MT;
    const int mi  = tid & 31;
    const int grp = tid >> 5;

    const float* Q = g_Q + (size_t)b * CHD * HW;
    const float* K = g_K + (size_t)b * CHD * HW;
    const float* V = g_V + (size_t)b * CIN * HW;

    // Load Q tile: Qs[c][m]
    {
        int ni = (tid & 15) * 4;
        for (int r = tid >> 4; r < CHD; r += 16)
            *(float4*)&Qs[r * 64 + ni] = *(const float4*)&Q[(size_t)r * HW + m0g + ni];
    }
    if (tid < 64) { rowmax[tid] = -1e30f; rowsum[tid] = 0.0f; }

    float acc0[32] = {}, acc1[32] = {};
    __syncthreads();

    for (int nt = 0; nt < HW; nt += NT) {
        // ---- load K tile: Ks[c][n] ----
        {
            int ni = (tid & 15) * 4;
            for (int r = tid >> 4; r < CHD; r += 16)
                *(float4*)&Ks[r * 64 + ni] = *(const float4*)&K[(size_t)r * HW + nt + ni];
        }
        __syncthreads();

        // ---- S = Q^T K  (2 m-rows x 8 n-cols per thread, K broadcast) ----
        float s0[8] = {}, s1[8] = {};
        {
            const float* kp = Ks + grp * 8;
            #pragma unroll 4
            for (int c = 0; c < CHD; c++) {
                float q0 = Qs[c * 64 + mi];
                float q1 = Qs[c * 64 + mi + 32];
                float4 ka = *(const float4*)&kp[c * 64];
                float4 kb = *(const float4*)&kp[c * 64 + 4];
                s0[0] += q0 * ka.x; s0[1] += q0 * ka.y; s0[2] += q0 * ka.z; s0[3] += q0 * ka.w;
                s0[4] += q0 * kb.x; s0[5] += q0 * kb.y; s0[6] += q0 * kb.z; s0[7] += q0 * kb.w;
                s1[0] += q1 * ka.x; s1[1] += q1 * ka.y; s1[2] += q1 * ka.z; s1[3] += q1 * ka.w;
                s1[4] += q1 * kb.x; s1[5] += q1 * kb.y; s1[6] += q1 * kb.z; s1[7] += q1 * kb.w;
            }
        }

        // ---- online softmax ----
        float lm0 = s0[0], lm1 = s1[0];
        #pragma unroll
        for (int j = 1; j < 8; j++) { lm0 = fmaxf(lm0, s0[j]); lm1 = fmaxf(lm1, s1[j]); }
        lmax[grp * 64 + mi]      = lm0;
        lmax[grp * 64 + mi + 32] = lm1;
        __syncthreads();

        if (tid < 64) {
            float mx = lmax[tid];
            #pragma unroll
            for (int g = 1; g < 8; g++) mx = fmaxf(mx, lmax[g * 64 + tid]);
            float om = rowmax[tid];
            float nm = fmaxf(om, mx);
            rowmax[tid] = nm;
            salpha[tid] = __expf(om - nm);
            snmax[tid]  = nm;
        }
        __syncthreads();

        {
            float nm0 = snmax[mi], nm1 = snmax[mi + 32];
            float ls0 = 0.0f, ls1 = 0.0f;
            #pragma unroll
            for (int j = 0; j < 8; j++) {
                float p0 = __expf(s0[j] - nm0);
                float p1 = __expf(s1[j] - nm1);
                ls0 += p0; ls1 += p1;
                Ss[(grp * 8 + j) * 64 + mi]      = p0;
                Ss[(grp * 8 + j) * 64 + mi + 32] = p1;
            }
            lsum[grp * 64 + mi]      = ls0;
            lsum[grp * 64 + mi + 32] = ls1;
        }
        __syncthreads();

        if (tid < 64) {
            float s = rowsum[tid] * salpha[tid];
            #pragma unroll
            for (int g = 0; g < 8; g++) s += lsum[g * 64 + tid];
            rowsum[tid] = s;
        }

        // ---- O accumulation: acc = acc*alpha + P . V^T ----
        {
            float al0 = salpha[mi], al1 = salpha[mi + 32];
            #pragma unroll
            for (int c = 0; c < 32; c++) { acc0[c] *= al0; acc1[c] *= al1; }

            const float* Vblk = V + (size_t)(grp * 32) * HW + nt;
            for (int nc = 0; nc < 16; nc++) {
                float p00 = Ss[(nc * 4 + 0) * 64 + mi];
                float p01 = Ss[(nc * 4 + 1) * 64 + mi];
                float p02 = Ss[(nc * 4 + 2) * 64 + mi];
                float p03 = Ss[(nc * 4 + 3) * 64 + mi];
                float p10 = Ss[(nc * 4 + 0) * 64 + mi + 32];
                float p11 = Ss[(nc * 4 + 1) * 64 + mi + 32];
                float p12 = Ss[(nc * 4 + 2) * 64 + mi + 32];
                float p13 = Ss[(nc * 4 + 3) * 64 + mi + 32];
                const float* vrow = Vblk + nc * 4;
                #pragma unroll
                for (int c = 0; c < 32; c++) {
                    float4 v = __ldg((const float4*)(vrow + (size_t)c * HW));
                    acc0[c] += p00 * v.x + p01 * v.y + p02 * v.z + p03 * v.w;
                    acc1[c] += p10 * v.x + p11 * v.y + p12 * v.z + p13 * v.w;
                }
            }
        }
        __syncthreads();   // protects Ks/Ss reuse next iteration; publishes rowsum
    }

    // ---- epilogue: normalize, add residual, coalesced stores ----
    const float inv0 = 1.0f / rowsum[mi];
    const float inv1 = 1.0f / rowsum[mi + 32];
    #pragma unroll
    for (int c = 0; c < 32; c++) {
        size_t base = ((size_t)b * CIN + grp * 32 + c) * HW + m0g;
        out[base + mi]      = acc0[c] * inv0 + resid[base + mi];
        out[base + mi + 32] = acc1[c] * inv1 + resid[base + mi + 32];
    }
}

// ---------------------------------------------------------------------------
extern "C" void kernel_launch(void* const* d_in, const int* in_sizes, int n_in,
                              void* d_out, int out_size) {
    const float* a  = (const float*)d_in[0];
    const float* p  = (const float*)d_in[1];
    const float* Wq = (const float*)d_in[2];
    const float* bq = (const float*)d_in[3];
    const float* Wk = (const float*)d_in[4];
    const float* bk = (const float*)d_in[5];
    const float* Wv = (const float*)d_in[6];
    const float* bv = (const float*)d_in[7];
    float* out = (float*)d_out;

    float *dQ, *dK, *dV;
    cudaGetSymbolAddress((void**)&dQ, g_Q);
    cudaGetSymbolAddress((void**)&dK, g_K);
    cudaGetSymbolAddress((void**)&dV, g_V);

    dim3 blk(256);
    proj_kernel<<<dim3(HW / 64, CHD / 64, BB), blk>>>(Wq, bq, a, dQ, CHD);
    proj_kernel<<<dim3(HW / 64, CHD / 64, BB), blk>>>(Wk, bk, p, dK, CHD);
    proj_kernel<<<dim3(HW / 64, CIN / 64, BB), blk>>>(Wv, bv, p, dV, CIN);

    const int smem = 21760 * 4;   // 87040 B
    static int attr_set = 0;
    cudaFuncSetAttribute(attn_kernel, cudaFuncAttributeMaxDynamicSharedMemorySize, smem);
    (void)attr_set;

    attn_kernel<<<dim3(HW / MT, BB), blk, smem>>>(a, out);
}

// round 6
// speedup vs baseline: 3.3959x; 3.3959x over previous
#include <cuda_runtime.h>
#include <cstddef>

#define HW   4096
#define CIN  256
#define CHD  128
#define BB   4
#define MT   128   // query tile per CTA
#define NT   64    // key tile per iteration

// Scratch (allocation-free device globals)
__device__ float g_Q[BB * HW * CHD];   // [b][m][c]  (transposed, tf32)
__device__ float g_K[BB * HW * CHD];   // [b][n][c]  (transposed, tf32)
__device__ float g_V[BB * CIN * HW];   // [b][cv][n] (tf32)

__device__ __forceinline__ float to_tf32(float x) {
    unsigned u;
    asm("cvt.rna.tf32.f32 %0, %1;" : "=r"(u) : "f"(x));
    return __uint_as_float(u);
}

__device__ __forceinline__ void mma_tf32(float c[4],
                                         unsigned a0, unsigned a1, unsigned a2, unsigned a3,
                                         unsigned b0, unsigned b1) {
    asm volatile(
        "mma.sync.aligned.m16n8k8.row.col.f32.tf32.tf32.f32 "
        "{%0,%1,%2,%3}, {%4,%5,%6,%7}, {%8,%9}, {%0,%1,%2,%3};\n"
        : "+f"(c[0]), "+f"(c[1]), "+f"(c[2]), "+f"(c[3])
        : "r"(a0), "r"(a1), "r"(a2), "r"(a3), "r"(b0), "r"(b1));
}

// ---------------------------------------------------------------------------
// V projection: Out[b, o, n] = sum_c W[o,c] X[b,c,n] + bias[o]   (tf32-rounded)
// ---------------------------------------------------------------------------
__global__ __launch_bounds__(256)
void proj_kernel(const float* __restrict__ W, const float* __restrict__ bias,
                 const float* __restrict__ X, float* __restrict__ Out, int O) {
    __shared__ float Ws[32][65];   // [k][o]
    __shared__ float Xs[32][64];   // [k][n]

    const int tid = threadIdx.x;
    const int n0  = blockIdx.x * 64;
    const int o0  = blockIdx.y * 64;
    const int b   = blockIdx.z;
    const float* Xb = X + (size_t)b * CIN * HW;

    const int tx = tid & 15;       // n quad
    const int ty = tid >> 4;       // o quad
    float acc[4][4] = {};

    for (int k0 = 0; k0 < CIN; k0 += 32) {
        {
            int r = tid >> 2;
            int q = (tid & 3) * 8;
            float4 wa = *(const float4*)&W[(size_t)(o0 + r) * CIN + k0 + q];
            float4 wb = *(const float4*)&W[(size_t)(o0 + r) * CIN + k0 + q + 4];
            Ws[q + 0][r] = wa.x; Ws[q + 1][r] = wa.y;
            Ws[q + 2][r] = wa.z; Ws[q + 3][r] = wa.w;
            Ws[q + 4][r] = wb.x; Ws[q + 5][r] = wb.y;
            Ws[q + 6][r] = wb.z; Ws[q + 7][r] = wb.w;
        }
        {
            int c  = tid >> 3;
            int nq = (tid & 7) * 8;
            const float* src = &Xb[(size_t)(k0 + c) * HW + n0 + nq];
            *(float4*)&Xs[c][nq]     = *(const float4*)&src[0];
            *(float4*)&Xs[c][nq + 4] = *(const float4*)&src[4];
        }
        __syncthreads();

        #pragma unroll
        for (int kk = 0; kk < 32; kk++) {
            float4 xv = *(float4*)&Xs[kk][tx * 4];
            float w0 = Ws[kk][ty * 4 + 0];
            float w1 = Ws[kk][ty * 4 + 1];
            float w2 = Ws[kk][ty * 4 + 2];
            float w3 = Ws[kk][ty * 4 + 3];
            acc[0][0] += w0 * xv.x; acc[0][1] += w0 * xv.y; acc[0][2] += w0 * xv.z; acc[0][3] += w0 * xv.w;
            acc[1][0] += w1 * xv.x; acc[1][1] += w1 * xv.y; acc[1][2] += w1 * xv.z; acc[1][3] += w1 * xv.w;
            acc[2][0] += w2 * xv.x; acc[2][1] += w2 * xv.y; acc[2][2] += w2 * xv.z; acc[2][3] += w2 * xv.w;
            acc[3][0] += w3 * xv.x; acc[3][1] += w3 * xv.y; acc[3][2] += w3 * xv.z; acc[3][3] += w3 * xv.w;
        }
        __syncthreads();
    }

    #pragma unroll
    for (int i = 0; i < 4; i++) {
        int o = o0 + ty * 4 + i;
        float bi = bias[o];
        float4 r;
        r.x = to_tf32(acc[i][0] + bi); r.y = to_tf32(acc[i][1] + bi);
        r.z = to_tf32(acc[i][2] + bi); r.w = to_tf32(acc[i][3] + bi);
        *(float4*)&Out[((size_t)b * O + o) * HW + n0 + tx * 4] = r;
    }
}

// ---------------------------------------------------------------------------
// Q/K projection, transposed output: Out[b, n, o] = sum_c W[o,c] X[b,c,n] + b[o]
// tx indexes o (coalesced stores over contiguous o), ty indexes n.
// ---------------------------------------------------------------------------
__global__ __launch_bounds__(256)
void proj_t_kernel(const float* __restrict__ W, const float* __restrict__ bias,
                   const float* __restrict__ X, float* __restrict__ Out, int O) {
    __shared__ float Ws[32][68];   // [k][o]  (pad 68: float4-aligned rows)
    __shared__ float Xs[32][64];   // [k][n]

    const int tid = threadIdx.x;
    const int n0  = blockIdx.x * 64;
    const int o0  = blockIdx.y * 64;
    const int b   = blockIdx.z;
    const float* Xb = X + (size_t)b * CIN * HW;

    const int tx = tid & 15;       // o quad
    const int ty = tid >> 4;       // n quad
    float acc[4][4] = {};          // [n-sub][o-vec]

    for (int k0 = 0; k0 < CIN; k0 += 32) {
        {
            int r = tid >> 2;
            int q = (tid & 3) * 8;
            float4 wa = *(const float4*)&W[(size_t)(o0 + r) * CIN + k0 + q];
            float4 wb = *(const float4*)&W[(size_t)(o0 + r) * CIN + k0 + q + 4];
            Ws[q + 0][r] = wa.x; Ws[q + 1][r] = wa.y;
            Ws[q + 2][r] = wa.z; Ws[q + 3][r] = wa.w;
            Ws[q + 4][r] = wb.x; Ws[q + 5][r] = wb.y;
            Ws[q + 6][r] = wb.z; Ws[q + 7][r] = wb.w;
        }
        {
            int c  = tid >> 3;
            int nq = (tid & 7) * 8;
            const float* src = &Xb[(size_t)(k0 + c) * HW + n0 + nq];
            *(float4*)&Xs[c][nq]     = *(const float4*)&src[0];
            *(float4*)&Xs[c][nq + 4] = *(const float4*)&src[4];
        }
        __syncthreads();

        #pragma unroll
        for (int kk = 0; kk < 32; kk++) {
            float4 wv = *(float4*)&Ws[kk][tx * 4];
            float x0 = Xs[kk][ty * 4 + 0];
            float x1 = Xs[kk][ty * 4 + 1];
            float x2 = Xs[kk][ty * 4 + 2];
            float x3 = Xs[kk][ty * 4 + 3];
            acc[0][0] += x0 * wv.x; acc[0][1] += x0 * wv.y; acc[0][2] += x0 * wv.z; acc[0][3] += x0 * wv.w;
            acc[1][0] += x1 * wv.x; acc[1][1] += x1 * wv.y; acc[1][2] += x1 * wv.z; acc[1][3] += x1 * wv.w;
            acc[2][0] += x2 * wv.x; acc[2][1] += x2 * wv.y; acc[2][2] += x2 * wv.z; acc[2][3] += x2 * wv.w;
            acc[3][0] += x3 * wv.x; acc[3][1] += x3 * wv.y; acc[3][2] += x3 * wv.z; acc[3][3] += x3 * wv.w;
        }
        __syncthreads();
    }

    float4 bb = *(const float4*)&bias[o0 + tx * 4];
    #pragma unroll
    for (int i = 0; i < 4; i++) {
        int n = n0 + ty * 4 + i;
        float4 r;
        r.x = to_tf32(acc[i][0] + bb.x); r.y = to_tf32(acc[i][1] + bb.y);
        r.z = to_tf32(acc[i][2] + bb.z); r.w = to_tf32(acc[i][3] + bb.w);
        *(float4*)&Out[((size_t)b * HW + n) * O + o0 + tx * 4] = r;
    }
}

// ---------------------------------------------------------------------------
// Flash attention with tf32 mma.sync + residual.
// grid (HW/128, B) = 128 CTAs (1 wave), 256 threads (8 warps), ~205KB smem.
//
// S-phase : S[128m][64n] = Q Kt     warps 4m x 2n, warp tile 32x32
// O-phase : O[128m][256cv] += P Vt  warps 4m x 2cv, warp tile 32x128
// m16n8k8 tf32 fragments: lane = 4g+t
//   A: a0(g,k t) a1(g+8,t) a2(g,t+4) a3(g+8,t+4);  B: b0(k t, n g) b1(t+4, g)
//   C: c0(g,2t) c1(g,2t+1) c2(g+8,2t) c3(g+8,2t+1)
// ---------------------------------------------------------------------------
__global__ __launch_bounds__(256)
void attn_kernel(const float* __restrict__ resid, float* __restrict__ out) {
    extern __shared__ float sm[];
    float* Qs     = sm;                 // [128][132]  16896
    float* Ks     = Qs + 128 * 132;     // [64][132]    8448
    float* Vs     = Ks + 64 * 132;      // [256][68]   17408
    float* Ps     = Vs + 256 * 68;      // [128][68]    8704
    float* rowM   = Ps + 128 * 68;      // 128
    float* rowL   = rowM + 128;         // 128
    float* alphaS = rowL + 128;         // 128
    float* pmax   = alphaS + 128;       // [2][128]
    float* psum   = pmax + 256;         // [2][128]

    const int tid  = threadIdx.x;
    const int b    = blockIdx.y;
    const int m0g  = blockIdx.x * MT;
    const int w    = tid >> 5;
    const int lane = tid & 31;
    const int g    = lane >> 2;
    const int t    = lane & 3;
    const int wm   = w & 3;        // m-quarter (both phases)
    const int wh   = w >> 2;       // n-half (S) / cv-half (O)
    const int m0w  = wm * 32;

    const float* Q = g_Q + (size_t)b * HW * CHD;
    const float* K = g_K + (size_t)b * HW * CHD;
    const float* V = g_V + (size_t)b * CIN * HW;

    // Load Q tile [128][128] -> Qs (rows padded to 132)
    for (int idx = tid; idx < 128 * 32; idx += 256) {
        int r = idx >> 5, c4 = (idx & 31) << 2;
        *(float4*)&Qs[r * 132 + c4] = *(const float4*)&Q[(size_t)(m0g + r) * CHD + c4];
    }
    if (tid < 128) { rowM[tid] = -1e30f; rowL[tid] = 0.0f; }

    float oacc[2][16][4];
    #pragma unroll
    for (int mf = 0; mf < 2; mf++)
        #pragma unroll
        for (int cf = 0; cf < 16; cf++)
            #pragma unroll
            for (int e = 0; e < 4; e++) oacc[mf][cf][e] = 0.0f;

    for (int nt = 0; nt < HW; nt += NT) {
        __syncthreads();   // prior O-MMA (reads Ps/Vs) done; Qs ready on iter 0

        // K tile [64][128] -> Ks
        for (int idx = tid; idx < 64 * 32; idx += 256) {
            int r = idx >> 5, c4 = (idx & 31) << 2;
            *(float4*)&Ks[r * 132 + c4] = *(const float4*)&K[(size_t)(nt + r) * CHD + c4];
        }
        // V tile [256][64] -> Vs (rows padded to 68)
        for (int idx = tid; idx < 256 * 16; idx += 256) {
            int r = idx >> 4, c4 = (idx & 15) << 2;
            *(float4*)&Vs[r * 68 + c4] = *(const float4*)&V[(size_t)r * HW + nt + c4];
        }
        __syncthreads();

        // ---- S = Q Kt ----
        float sacc[2][4][4] = {};
        const int n0w = wh * 32;
        #pragma unroll
        for (int ks = 0; ks < 16; ks++) {
            int kc = ks * 8;
            unsigned a[2][4];
            #pragma unroll
            for (int mf = 0; mf < 2; mf++) {
                int r = m0w + mf * 16 + g;
                a[mf][0] = __float_as_uint(Qs[r * 132 + kc + t]);
                a[mf][1] = __float_as_uint(Qs[(r + 8) * 132 + kc + t]);
                a[mf][2] = __float_as_uint(Qs[r * 132 + kc + t + 4]);
                a[mf][3] = __float_as_uint(Qs[(r + 8) * 132 + kc + t + 4]);
            }
            #pragma unroll
            for (int nf = 0; nf < 4; nf++) {
                int n = n0w + nf * 8 + g;
                unsigned b0 = __float_as_uint(Ks[n * 132 + kc + t]);
                unsigned b1 = __float_as_uint(Ks[n * 132 + kc + t + 4]);
                mma_tf32(sacc[0][nf], a[0][0], a[0][1], a[0][2], a[0][3], b0, b1);
                mma_tf32(sacc[1][nf], a[1][0], a[1][1], a[1][2], a[1][3], b0, b1);
            }
        }

        // ---- softmax: per-warp partial row max ----
        #pragma unroll
        for (int mf = 0; mf < 2; mf++) {
            float lm0 = -1e30f, lm1 = -1e30f;
            #pragma unroll
            for (int nf = 0; nf < 4; nf++) {
                lm0 = fmaxf(lm0, fmaxf(sacc[mf][nf][0], sacc[mf][nf][1]));
                lm1 = fmaxf(lm1, fmaxf(sacc[mf][nf][2], sacc[mf][nf][3]));
            }
            lm0 = fmaxf(lm0, __shfl_xor_sync(0xffffffffu, lm0, 1));
            lm0 = fmaxf(lm0, __shfl_xor_sync(0xffffffffu, lm0, 2));
            lm1 = fmaxf(lm1, __shfl_xor_sync(0xffffffffu, lm1, 1));
            lm1 = fmaxf(lm1, __shfl_xor_sync(0xffffffffu, lm1, 2));
            if (t == 0) {
                pmax[wh * 128 + m0w + mf * 16 + g]     = lm0;
                pmax[wh * 128 + m0w + mf * 16 + g + 8] = lm1;
            }
        }
        __syncthreads();

        if (tid < 128) {
            float mx = fmaxf(pmax[tid], pmax[128 + tid]);
            float om = rowM[tid];
            float nm = fmaxf(om, mx);
            rowM[tid]   = nm;
            alphaS[tid] = __expf(om - nm);
        }
        __syncthreads();

        // ---- P = exp(S - m), tf32-round, store + partial sums ----
        #pragma unroll
        for (int mf = 0; mf < 2; mf++) {
            int r0 = m0w + mf * 16 + g;
            float nm0 = rowM[r0], nm1 = rowM[r0 + 8];
            float ls0 = 0.0f, ls1 = 0.0f;
            #pragma unroll
            for (int nf = 0; nf < 4; nf++) {
                float p0 = to_tf32(__expf(sacc[mf][nf][0] - nm0));
                float p1 = to_tf32(__expf(sacc[mf][nf][1] - nm0));
                float p2 = to_tf32(__expf(sacc[mf][nf][2] - nm1));
                float p3 = to_tf32(__expf(sacc[mf][nf][3] - nm1));
                ls0 += p0 + p1;
                ls1 += p2 + p3;
                int n = n0w + nf * 8 + 2 * t;
                *(float2*)&Ps[r0 * 68 + n]       = make_float2(p0, p1);
                *(float2*)&Ps[(r0 + 8) * 68 + n] = make_float2(p2, p3);
            }
            ls0 += __shfl_xor_sync(0xffffffffu, ls0, 1);
            ls0 += __shfl_xor_sync(0xffffffffu, ls0, 2);
            ls1 += __shfl_xor_sync(0xffffffffu, ls1, 1);
            ls1 += __shfl_xor_sync(0xffffffffu, ls1, 2);
            if (t == 0) {
                psum[wh * 128 + r0]     = ls0;
                psum[wh * 128 + r0 + 8] = ls1;
            }
        }
        __syncthreads();

        if (tid < 128)
            rowL[tid] = rowL[tid] * alphaS[tid] + psum[tid] + psum[128 + tid];

        // ---- O = O*alpha + P Vt ----
        #pragma unroll
        for (int mf = 0; mf < 2; mf++) {
            float al0 = alphaS[m0w + mf * 16 + g];
            float al1 = alphaS[m0w + mf * 16 + g + 8];
            #pragma unroll
            for (int cf = 0; cf < 16; cf++) {
                oacc[mf][cf][0] *= al0; oacc[mf][cf][1] *= al0;
                oacc[mf][cf][2] *= al1; oacc[mf][cf][3] *= al1;
            }
        }
        const int cv0w = wh * 128;
        #pragma unroll
        for (int kn = 0; kn < 8; kn++) {
            int kc = kn * 8;
            unsigned a[2][4];
            #pragma unroll
            for (int mf = 0; mf < 2; mf++) {
                int r = m0w + mf * 16 + g;
                a[mf][0] = __float_as_uint(Ps[r * 68 + kc + t]);
                a[mf][1] = __float_as_uint(Ps[(r + 8) * 68 + kc + t]);
                a[mf][2] = __float_as_uint(Ps[r * 68 + kc + t + 4]);
                a[mf][3] = __float_as_uint(Ps[(r + 8) * 68 + kc + t + 4]);
            }
            #pragma unroll
            for (int cf = 0; cf < 16; cf++) {
                int cv = cv0w + cf * 8 + g;
                unsigned b0 = __float_as_uint(Vs[cv * 68 + kc + t]);
                unsigned b1 = __float_as_uint(Vs[cv * 68 + kc + t + 4]);
                mma_tf32(oacc[0][cf], a[0][0], a[0][1], a[0][2], a[0][3], b0, b1);
                mma_tf32(oacc[1][cf], a[1][0], a[1][1], a[1][2], a[1][3], b0, b1);
            }
        }
    }
    __syncthreads();

    // ---- epilogue: normalize, residual, store ----
    {
        const int cv0w = wh * 128;
        #pragma unroll
        for (int mf = 0; mf < 2; mf++) {
            int r0 = m0w + mf * 16 + g;
            float il0 = 1.0f / rowL[r0];
            float il1 = 1.0f / rowL[r0 + 8];
            int mg = m0g + r0;
            #pragma unroll
            for (int cf = 0; cf < 16; cf++) {
                int cv = cv0w + cf * 8 + 2 * t;
                size_t i0 = ((size_t)(b * CIN + cv)) * HW + mg;
                size_t i1 = i0 + HW;
                out[i0]     = oacc[mf][cf][0] * il0 + resid[i0];
                out[i1]     = oacc[mf][cf][1] * il0 + resid[i1];
                out[i0 + 8] = oacc[mf][cf][2] * il1 + resid[i0 + 8];
                out[i1 + 8] = oacc[mf][cf][3] * il1 + resid[i1 + 8];
            }
        }
    }
}

// ---------------------------------------------------------------------------
extern "C" void kernel_launch(void* const* d_in, const int* in_sizes, int n_in,
                              void* d_out, int out_size) {
    const float* a  = (const float*)d_in[0];
    const float* p  = (const float*)d_in[1];
    const float* Wq = (const float*)d_in[2];
    const float* bq = (const float*)d_in[3];
    const float* Wk = (const float*)d_in[4];
    const float* bk = (const float*)d_in[5];
    const float* Wv = (const float*)d_in[6];
    const float* bv = (const float*)d_in[7];
    float* out = (float*)d_out;

    float *dQ, *dK, *dV;
    cudaGetSymbolAddress((void**)&dQ, g_Q);
    cudaGetSymbolAddress((void**)&dK, g_K);
    cudaGetSymbolAddress((void**)&dV, g_V);

    dim3 blk(256);
    proj_t_kernel<<<dim3(HW / 64, CHD / 64, BB), blk>>>(Wq, bq, a, dQ, CHD);
    proj_t_kernel<<<dim3(HW / 64, CHD / 64, BB), blk>>>(Wk, bk, p, dK, CHD);
    proj_kernel  <<<dim3(HW / 64, CIN / 64, BB), blk>>>(Wv, bv, p, dV, CIN);

    const int smem = (128 * 132 + 64 * 132 + 256 * 68 + 128 * 68 + 128 * 3 + 512) * 4; // 209408
    cudaFuncSetAttribute(attn_kernel, cudaFuncAttributeMaxDynamicSharedMemorySize, smem);
    attn_kernel<<<dim3(HW / MT, BB), blk, smem>>>(a, out);
}